// round 10
// baseline (speedup 1.0000x reference)
#include <cuda_runtime.h>
#include <cstdint>

// Verblizer: per-token argmax(20) -> expert Linear(2,2) -> softmax(2) -> y,
// plus permuted copy y2 (pu rows first, then non-pu rows in order).
// d_out[0..2S) = y, d_out[2S..4S) = y2.
//
// Structure (R8 + persistent blocks):
//   1) lb_scatter (PDL-triggered): g_lb0[j] = lower_bound(pu, j*CHUNK)
//   2) verblizer_kernel: persistent grid (592 blocks), each loops over
//      chunks; cp.async pipeline stays warm across chunk boundaries
//      (next chunk's tile-0 + spu window prefetched during last tile).

#define THREADS 256
#define TILE    256
#define NTILES  4
#define CHUNK   (TILE * NTILES)      // 1024 tokens per chunk
#define MAXB    65537
#define PBLOCKS 592                  // 148 SMs x 4 resident blocks

__device__ int g_lb0[MAXB];

// ---- vectorized streaming scatter: each thread owns pu[8i .. 8i+8) ----
__global__ void lb_scatter(const int* __restrict__ pu, int P, int nblocks)
{
    const int i = blockIdx.x * blockDim.x + threadIdx.x;
    const int base = i * 8;
    if (base < P) {
        int v[9];
        const int4 a = __ldg(reinterpret_cast<const int4*>(pu) + 2 * i);
        v[0] = a.x; v[1] = a.y; v[2] = a.z; v[3] = a.w;
        if (base + 8 <= P) {
            const int4 c = __ldg(reinterpret_cast<const int4*>(pu) + 2 * i + 1);
            v[4] = c.x; v[5] = c.y; v[6] = c.z; v[7] = c.w;
            v[8] = (base + 8 < P) ? __ldg(pu + base + 8) : 0x7fffffff;
        } else {
            #pragma unroll
            for (int k = 4; k <= 8; k++)
                v[k] = (base + k < P) ? __ldg(pu + base + k) : 0x7fffffff;
        }

        if (i == 0) {
            for (int j = 0; j <= nblocks && j * CHUNK <= v[0]; j++) g_lb0[j] = 0;
        }

        #pragma unroll
        for (int k = 0; k < 8; k++) {
            const int m = base + k;
            if (m >= P) break;
            const int hiv = v[k + 1];
            int j  = v[k] / CHUNK + 1;
            int jh = (hiv == 0x7fffffff) ? nblocks : hiv / CHUNK;
            if (jh > nblocks) jh = nblocks;
            for (; j <= jh; j++) g_lb0[j] = m + 1;
        }
    }
    cudaTriggerProgrammaticLaunchCompletion();
}

__device__ __forceinline__ void cp_async16(uint32_t smem_dst, const void* gptr) {
    asm volatile("cp.async.cg.shared.global [%0], [%1], 16;\n" :: "r"(smem_dst), "l"(gptr));
}
__device__ __forceinline__ void cp_commit() { asm volatile("cp.async.commit_group;\n"); }
template<int N> __device__ __forceinline__ void cp_wait() {
    asm volatile("cp.async.wait_group %0;\n" :: "n"(N));
}

__global__ __launch_bounds__(THREADS)
void verblizer_kernel(const float*  __restrict__ x,
                      const float*  __restrict__ h,
                      const float*  __restrict__ W,
                      const float*  __restrict__ b,
                      const int*    __restrict__ pu,
                      int S, int P, int nchunks,
                      float* __restrict__ out)
{
    __shared__ float4 sx[2][TILE * 5];   // 2 x 20KB staged x tiles
    __shared__ int    spu[2][CHUNK];     // 2 x 4KB pu windows (cur/next chunk)
    __shared__ float4 sW[20];
    __shared__ float2 sB[20];

    const int tid = threadIdx.x;
    const int G   = gridDim.x;

    if (tid < 20) {
        sW[tid] = reinterpret_cast<const float4*>(W)[tid];
        sB[tid] = reinterpret_cast<const float2*>(b)[tid];
    }

    const char* __restrict__ xb = reinterpret_cast<const char*>(x);
    const float2* __restrict__ h2 = reinterpret_cast<const float2*>(h);
    float2* __restrict__ outy  = reinterpret_cast<float2*>(out);
    float2* __restrict__ outy2 = reinterpret_cast<float2*>(out + (size_t)2 * S);

    int c = blockIdx.x;
    if (c >= nchunks) return;

    // ---- stage tile-0 of first chunk (x only; independent of g_lb0) ----
    {
        const int tb  = c * CHUNK;
        const int vt  = min(TILE, S - tb);
        const int vt5 = vt * 5;
        uint32_t dst = (uint32_t)__cvta_generic_to_shared(&sx[0][0]);
        #pragma unroll
        for (int r = 0; r < 5; r++) {
            const int cc = tid + r * THREADS;
            if (cc < vt5) cp_async16(dst + cc * 16, xb + (size_t)tb * 80 + (size_t)cc * 16);
        }
        cp_commit();
    }

    // ---- wait for lb_scatter (PDL) then stage first chunk's pu window ----
    cudaGridDependencySynchronize();

    int lb0 = g_lb0[c];
    int n   = g_lb0[c + 1] - lb0;
    for (int i = tid; i < n; i += THREADS) spu[0][i] = __ldg(pu + lb0 + i);

    int xbuf = 0, pbuf = 0;
    int lb0n = 0, nn = 0;

    for (; c < nchunks; c += G) {
        const int cn = c + G;   // this block's next chunk

        #pragma unroll
        for (int t = 0; t < NTILES; t++) {
            // ---- prefetch next tile (same chunk, or tile-0 of next chunk) ----
            int  ntb;
            bool have;
            if (t + 1 < NTILES) { ntb = c * CHUNK + (t + 1) * TILE; have = (ntb < S); }
            else                { ntb = cn * CHUNK;                 have = (cn < nchunks); }
            if (have) {
                const int vt  = min(TILE, S - ntb);
                const int vt5 = vt * 5;
                uint32_t dst = (uint32_t)__cvta_generic_to_shared(&sx[xbuf ^ 1][0]);
                #pragma unroll
                for (int r = 0; r < 5; r++) {
                    const int cc = tid + r * THREADS;
                    if (cc < vt5) cp_async16(dst + cc * 16, xb + (size_t)ntb * 80 + (size_t)cc * 16);
                }
                cp_commit();
                cp_wait<1>();
            } else {
                cp_wait<0>();
            }

            // ---- prefetch next chunk's pu window during the last tile ----
            if (t == NTILES - 1 && cn < nchunks) {
                lb0n = g_lb0[cn];                        // broadcast L2 reads
                nn   = g_lb0[cn + 1] - lb0n;
                for (int i = tid; i < nn; i += THREADS)
                    spu[pbuf ^ 1][i] = __ldg(pu + lb0n + i);
            }
            __syncthreads();

            const int s = c * CHUNK + t * TILE + tid;
            if (s < S) {
                const float4* __restrict__ row = &sx[xbuf][tid * 5];

                // ---- exact argmax over 20 f32 (first-index tie-break) ----
                const float4 q0 = row[0], q1 = row[1], q2 = row[2], q3 = row[3], q4 = row[4];
                const float g0 = fmaxf(fmaxf(q0.x, q0.y), fmaxf(q0.z, q0.w));
                const float g1 = fmaxf(fmaxf(q1.x, q1.y), fmaxf(q1.z, q1.w));
                const float g2 = fmaxf(fmaxf(q2.x, q2.y), fmaxf(q2.z, q2.w));
                const float g3 = fmaxf(fmaxf(q3.x, q3.y), fmaxf(q3.z, q3.w));
                const float g4 = fmaxf(fmaxf(q4.x, q4.y), fmaxf(q4.z, q4.w));
                const float M  = fmaxf(g4, fmaxf(fmaxf(g0, g1), fmaxf(g2, g3)));

                int gi = 4;
                gi = (g3 == M) ? 3 : gi;
                gi = (g2 == M) ? 2 : gi;
                gi = (g1 == M) ? 1 : gi;
                gi = (g0 == M) ? 0 : gi;

                const float4 qw = row[gi];       // LDS reload of winning quad
                int li = 3;
                li = (qw.z == M) ? 2 : li;
                li = (qw.y == M) ? 1 : li;
                li = (qw.x == M) ? 0 : li;
                const int e = gi * 4 + li;

                // ---- expert Linear(2,2) + softmax(2) ----
                const float2 hv = h2[s];
                const float4 w  = sW[e];
                const float2 bb = sB[e];
                const float y0 = fmaf(hv.x, w.x, fmaf(hv.y, w.y, bb.x));
                const float y1 = fmaf(hv.x, w.z, fmaf(hv.y, w.w, bb.y));
                const float ed  = __expf(y1 - y0);
                const float inv = __fdividef(1.0f, 1.0f + ed);
                float2 yo;
                yo.x = inv;
                yo.y = ed * inv;

                outy[s] = yo;

                // ---- permutation: lb = lb0 + lower_bound(spu[pbuf], s) ----
                const int* __restrict__ pw = spu[pbuf];
                int lo = 0, hi = n;
                while (lo < hi) {
                    int mid = (lo + hi) >> 1;
                    if (pw[mid] < s) lo = mid + 1; else hi = mid;
                }
                const int  cur  = (lo < n) ? pw[lo] : 0x7fffffff;
                const bool ispu = (cur == s);
                const int  dest = ispu ? (lb0 + lo) : (P + s - lb0 - lo);
                outy2[dest] = yo;
            }
            xbuf ^= 1;
            __syncthreads();
        }

        lb0 = lb0n; n = nn; pbuf ^= 1;
    }
}

extern "C" void kernel_launch(void* const* d_in, const int* in_sizes, int n_in,
                              void* d_out, int out_size)
{
    const float* x  = (const float*)d_in[0];   // [1, S, 20]
    const float* h  = (const float*)d_in[1];   // [S, 2]
    const float* W  = (const float*)d_in[2];   // [20, 2, 2]
    const float* b  = (const float*)d_in[3];   // [20, 2]
    const int*   pu = (const int*)  d_in[4];   // [P]

    const int S = in_sizes[1] / 2;
    const int P = in_sizes[4];
    const int nchunks = (S + CHUNK - 1) / CHUNK;
    const int blocks  = (nchunks < PBLOCKS) ? nchunks : PBLOCKS;

    const int sthreads = (P + 7) / 8;
    lb_scatter<<<(sthreads + 255) / 256, 256>>>(pu, P, nchunks);

    cudaLaunchAttribute attrs[1];
    attrs[0].id = cudaLaunchAttributeProgrammaticStreamSerialization;
    attrs[0].val.programmaticStreamSerializationAllowed = 1;

    cudaLaunchConfig_t cfg = {};
    cfg.gridDim  = dim3((unsigned)blocks, 1, 1);
    cfg.blockDim = dim3(THREADS, 1, 1);
    cfg.dynamicSmemBytes = 0;
    cfg.stream = 0;
    cfg.attrs = attrs;
    cfg.numAttrs = 1;

    cudaLaunchKernelEx(&cfg, verblizer_kernel, x, h, W, b, pu, S, P, nchunks, (float*)d_out);
}

// round 11
// speedup vs baseline: 1.0319x; 1.0319x over previous
#include <cuda_runtime.h>
#include <cstdint>

// Verblizer: per-token argmax(20) -> expert Linear(2,2) -> softmax(2) -> y,
// plus permuted copy y2 (pu rows first, then non-pu rows in order).
// d_out[0..2S) = y, d_out[2S..4S) = y2.
//
// R8 structure (proven): lb_scatter (PDL-triggered) + independent blocks.
// NEW: per-token rank via smem bitmap + popcount (replaces the 10-step
// LDS binary search); smem drops 46->42.4KB -> 5 blocks/SM.

#define THREADS 256
#define TILE    256
#define NTILES  4
#define CHUNK   (TILE * NTILES)      // 1024 tokens per block
#define NWORDS  (CHUNK / 32)         // 32 bitmap words
#define MAXB    65537

__device__ int g_lb0[MAXB];

// ---- vectorized streaming scatter: each thread owns pu[8i .. 8i+8) ----
__global__ void lb_scatter(const int* __restrict__ pu, int P, int nblocks)
{
    const int i = blockIdx.x * blockDim.x + threadIdx.x;
    const int base = i * 8;
    if (base < P) {
        int v[9];
        const int4 a = __ldg(reinterpret_cast<const int4*>(pu) + 2 * i);
        v[0] = a.x; v[1] = a.y; v[2] = a.z; v[3] = a.w;
        if (base + 8 <= P) {
            const int4 c = __ldg(reinterpret_cast<const int4*>(pu) + 2 * i + 1);
            v[4] = c.x; v[5] = c.y; v[6] = c.z; v[7] = c.w;
            v[8] = (base + 8 < P) ? __ldg(pu + base + 8) : 0x7fffffff;
        } else {
            #pragma unroll
            for (int k = 4; k <= 8; k++)
                v[k] = (base + k < P) ? __ldg(pu + base + k) : 0x7fffffff;
        }

        if (i == 0) {
            for (int j = 0; j <= nblocks && j * CHUNK <= v[0]; j++) g_lb0[j] = 0;
        }

        #pragma unroll
        for (int k = 0; k < 8; k++) {
            const int m = base + k;
            if (m >= P) break;
            const int hiv = v[k + 1];
            int j  = v[k] / CHUNK + 1;
            int jh = (hiv == 0x7fffffff) ? nblocks : hiv / CHUNK;
            if (jh > nblocks) jh = nblocks;
            for (; j <= jh; j++) g_lb0[j] = m + 1;
        }
    }
    cudaTriggerProgrammaticLaunchCompletion();
}

__device__ __forceinline__ void cp_async16(uint32_t smem_dst, const void* gptr) {
    asm volatile("cp.async.cg.shared.global [%0], [%1], 16;\n" :: "r"(smem_dst), "l"(gptr));
}
__device__ __forceinline__ void cp_commit() { asm volatile("cp.async.commit_group;\n"); }
template<int N> __device__ __forceinline__ void cp_wait() {
    asm volatile("cp.async.wait_group %0;\n" :: "n"(N));
}

__global__ __launch_bounds__(THREADS)
void verblizer_kernel(const float*  __restrict__ x,
                      const float*  __restrict__ h,
                      const float*  __restrict__ W,
                      const float*  __restrict__ b,
                      const int*    __restrict__ pu,
                      int S, int P,
                      float* __restrict__ out)
{
    __shared__ float4   sx[2][TILE * 5];   // 2 x 20KB staged x tiles
    __shared__ unsigned sbit[NWORDS];      // pu membership bitmap (128B)
    __shared__ int      spre[NWORDS];      // exclusive prefix of popcounts (128B)
    __shared__ float4   sW[20];
    __shared__ float2   sB[20];

    const int tid = threadIdx.x;
    const int bs  = blockIdx.x * CHUNK;

    // ---- prelude: independent of g_lb0 (overlaps scatter via PDL) ----
    if (tid < 20) {
        sW[tid] = reinterpret_cast<const float4*>(W)[tid];
        sB[tid] = reinterpret_cast<const float2*>(b)[tid];
    }
    if (tid < NWORDS) sbit[tid] = 0u;

    const char* __restrict__ xb = reinterpret_cast<const char*>(x);
    const float2* __restrict__ h2 = reinterpret_cast<const float2*>(h);
    float2* __restrict__ outy  = reinterpret_cast<float2*>(out);
    float2* __restrict__ outy2 = reinterpret_cast<float2*>(out + (size_t)2 * S);

    // stage tile 0 (x stream only)
    {
        const int vt  = min(TILE, S - bs);
        const int vt5 = vt * 5;
        uint32_t dst = (uint32_t)__cvta_generic_to_shared(&sx[0][0]);
        #pragma unroll
        for (int r = 0; r < 5; r++) {
            const int c = tid + r * THREADS;
            if (c < vt5) cp_async16(dst + c * 16, xb + (size_t)bs * 80 + (size_t)c * 16);
        }
        cp_commit();
    }

    __syncthreads();                      // bitmap zeroing visible before atomicOr

    // ---- wait for lb_scatter's g_lb0, then build bitmap ----
    cudaGridDependencySynchronize();

    const int lb0 = g_lb0[blockIdx.x];
    const int n   = g_lb0[blockIdx.x + 1] - lb0;   // pu entries in window (<= CHUNK)

    for (int i = tid; i < n; i += THREADS) {
        const int pos = __ldg(pu + lb0 + i) - bs;  // in [0, CHUNK)
        atomicOr(&sbit[pos >> 5], 1u << (pos & 31));
    }
    __syncthreads();                      // bitmap complete

    // warp 0: exclusive prefix of word popcounts (NWORDS = 32)
    if (tid < 32) {
        int c = __popc(sbit[tid]);
        int sc = c;
        #pragma unroll
        for (int o = 1; o < 32; o <<= 1) {
            int u = __shfl_up_sync(0xffffffffu, sc, o);
            if (tid >= o) sc += u;
        }
        spre[tid] = sc - c;               // exclusive
    }
    // visibility of spre: first in-loop __syncthreads below

    #pragma unroll
    for (int t = 0; t < NTILES; t++) {
        if (t + 1 < NTILES) {
            const int tb  = bs + (t + 1) * TILE;
            const int vt  = min(TILE, S - tb);
            const int vt5 = vt * 5;
            uint32_t dst = (uint32_t)__cvta_generic_to_shared(&sx[(t + 1) & 1][0]);
            #pragma unroll
            for (int r = 0; r < 5; r++) {
                const int c = tid + r * THREADS;
                if (c < vt5) cp_async16(dst + c * 16, xb + (size_t)tb * 80 + (size_t)c * 16);
            }
            cp_commit();
            cp_wait<1>();
        } else {
            cp_wait<0>();
        }
        __syncthreads();

        const int s = bs + t * TILE + tid;
        if (s < S) {
            const float4* __restrict__ row = &sx[t & 1][tid * 5];

            // ---- exact argmax over 20 f32 (first-index tie-break) ----
            const float4 q0 = row[0], q1 = row[1], q2 = row[2], q3 = row[3], q4 = row[4];
            const float g0 = fmaxf(fmaxf(q0.x, q0.y), fmaxf(q0.z, q0.w));
            const float g1 = fmaxf(fmaxf(q1.x, q1.y), fmaxf(q1.z, q1.w));
            const float g2 = fmaxf(fmaxf(q2.x, q2.y), fmaxf(q2.z, q2.w));
            const float g3 = fmaxf(fmaxf(q3.x, q3.y), fmaxf(q3.z, q3.w));
            const float g4 = fmaxf(fmaxf(q4.x, q4.y), fmaxf(q4.z, q4.w));
            const float M  = fmaxf(g4, fmaxf(fmaxf(g0, g1), fmaxf(g2, g3)));

            int gi = 4;
            gi = (g3 == M) ? 3 : gi;
            gi = (g2 == M) ? 2 : gi;
            gi = (g1 == M) ? 1 : gi;
            gi = (g0 == M) ? 0 : gi;

            const float4 qw = row[gi];           // LDS reload of winning quad
            int li = 3;
            li = (qw.z == M) ? 2 : li;
            li = (qw.y == M) ? 1 : li;
            li = (qw.x == M) ? 0 : li;
            const int e = gi * 4 + li;

            // ---- expert Linear(2,2) + softmax(2) ----
            const float2 hv = h2[s];
            const float4 w  = sW[e];
            const float2 bb = sB[e];
            const float y0 = fmaf(hv.x, w.x, fmaf(hv.y, w.y, bb.x));
            const float y1 = fmaf(hv.x, w.z, fmaf(hv.y, w.w, bb.y));
            const float ed  = __expf(y1 - y0);
            const float inv = __fdividef(1.0f, 1.0f + ed);
            float2 yo;
            yo.x = inv;
            yo.y = ed * inv;

            outy[s] = yo;

            // ---- permutation via bitmap rank ----
            const int pos  = t * TILE + tid;           // position within chunk
            const unsigned word = sbit[pos >> 5];
            const unsigned below = word & ((1u << (pos & 31)) - 1u);
            const int  lb   = lb0 + spre[pos >> 5] + __popc(below);
            const bool ispu = (word >> (pos & 31)) & 1u;
            const int  dest = ispu ? lb : (P + s - lb);
            outy2[dest] = yo;
        }
        __syncthreads();
    }
}

extern "C" void kernel_launch(void* const* d_in, const int* in_sizes, int n_in,
                              void* d_out, int out_size)
{
    const float* x  = (const float*)d_in[0];   // [1, S, 20]
    const float* h  = (const float*)d_in[1];   // [S, 2]
    const float* W  = (const float*)d_in[2];   // [20, 2, 2]
    const float* b  = (const float*)d_in[3];   // [20, 2]
    const int*   pu = (const int*)  d_in[4];   // [P]

    const int S = in_sizes[1] / 2;
    const int P = in_sizes[4];
    const int blocks = (S + CHUNK - 1) / CHUNK;

    const int sthreads = (P + 7) / 8;
    lb_scatter<<<(sthreads + 255) / 256, 256>>>(pu, P, blocks);

    cudaLaunchAttribute attrs[1];
    attrs[0].id = cudaLaunchAttributeProgrammaticStreamSerialization;
    attrs[0].val.programmaticStreamSerializationAllowed = 1;

    cudaLaunchConfig_t cfg = {};
    cfg.gridDim  = dim3((unsigned)blocks, 1, 1);
    cfg.blockDim = dim3(THREADS, 1, 1);
    cfg.dynamicSmemBytes = 0;
    cfg.stream = 0;
    cfg.attrs = attrs;
    cfg.numAttrs = 1;

    cudaLaunchKernelEx(&cfg, verblizer_kernel, x, h, W, b, pu, S, P, (float*)d_out);
}

// round 12
// speedup vs baseline: 1.0334x; 1.0015x over previous
#include <cuda_runtime.h>
#include <cstdint>

// Verblizer: per-token argmax(20) -> expert Linear(2,2) -> softmax(2) -> y,
// plus permuted copy y2 (pu rows first, then non-pu rows in order).
// d_out[0..2S) = y, d_out[2S..4S) = y2.
//
// R8 structure (proven best): lb_scatter (PDL) + independent streaming blocks.
// R12 deltas: CHUNK 1024->2048 (halves block count), spu staged as u16
// offsets (smem ~44.6KB -> 5 blocks/SM).

#define THREADS 256
#define TILE    256
#define NTILES  8
#define CHUNK   (TILE * NTILES)      // 2048 tokens per block
#define MAXB    65537

__device__ int g_lb0[MAXB];

// ---- vectorized streaming scatter: each thread owns pu[8i .. 8i+8) ----
__global__ void lb_scatter(const int* __restrict__ pu, int P, int nblocks)
{
    const int i = blockIdx.x * blockDim.x + threadIdx.x;
    const int base = i * 8;
    if (base < P) {
        int v[9];
        const int4 a = __ldg(reinterpret_cast<const int4*>(pu) + 2 * i);
        v[0] = a.x; v[1] = a.y; v[2] = a.z; v[3] = a.w;
        if (base + 8 <= P) {
            const int4 c = __ldg(reinterpret_cast<const int4*>(pu) + 2 * i + 1);
            v[4] = c.x; v[5] = c.y; v[6] = c.z; v[7] = c.w;
            v[8] = (base + 8 < P) ? __ldg(pu + base + 8) : 0x7fffffff;
        } else {
            #pragma unroll
            for (int k = 4; k <= 8; k++)
                v[k] = (base + k < P) ? __ldg(pu + base + k) : 0x7fffffff;
        }

        if (i == 0) {
            for (int j = 0; j <= nblocks && j * CHUNK <= v[0]; j++) g_lb0[j] = 0;
        }

        #pragma unroll
        for (int k = 0; k < 8; k++) {
            const int m = base + k;
            if (m >= P) break;
            const int hiv = v[k + 1];
            int j  = v[k] / CHUNK + 1;
            int jh = (hiv == 0x7fffffff) ? nblocks : hiv / CHUNK;
            if (jh > nblocks) jh = nblocks;
            for (; j <= jh; j++) g_lb0[j] = m + 1;
        }
    }
    cudaTriggerProgrammaticLaunchCompletion();
}

__device__ __forceinline__ void cp_async16(uint32_t smem_dst, const void* gptr) {
    asm volatile("cp.async.cg.shared.global [%0], [%1], 16;\n" :: "r"(smem_dst), "l"(gptr));
}
__device__ __forceinline__ void cp_commit() { asm volatile("cp.async.commit_group;\n"); }
template<int N> __device__ __forceinline__ void cp_wait() {
    asm volatile("cp.async.wait_group %0;\n" :: "n"(N));
}

__global__ __launch_bounds__(THREADS)
void verblizer_kernel(const float*  __restrict__ x,
                      const float*  __restrict__ h,
                      const float*  __restrict__ W,
                      const float*  __restrict__ b,
                      const int*    __restrict__ pu,
                      int S, int P,
                      float* __restrict__ out)
{
    __shared__ float4   sx[2][TILE * 5];   // 2 x 20KB staged x tiles
    __shared__ uint16_t spu[CHUNK];        // 4KB pu window (offsets from bs)
    __shared__ float4   sW[20];
    __shared__ float2   sB[20];

    const int tid = threadIdx.x;
    const int bs  = blockIdx.x * CHUNK;

    // ---- prelude: independent of g_lb0, overlaps the scatter kernel ----
    if (tid < 20) {
        sW[tid] = reinterpret_cast<const float4*>(W)[tid];
        sB[tid] = reinterpret_cast<const float2*>(b)[tid];
    }

    const char* __restrict__ xb = reinterpret_cast<const char*>(x);
    const float2* __restrict__ h2 = reinterpret_cast<const float2*>(h);
    float2* __restrict__ outy  = reinterpret_cast<float2*>(out);
    float2* __restrict__ outy2 = reinterpret_cast<float2*>(out + (size_t)2 * S);

    // stage tile 0 (x stream only)
    {
        const int vt  = min(TILE, S - bs);
        const int vt5 = vt * 5;
        uint32_t dst = (uint32_t)__cvta_generic_to_shared(&sx[0][0]);
        #pragma unroll
        for (int r = 0; r < 5; r++) {
            const int c = tid + r * THREADS;
            if (c < vt5) cp_async16(dst + c * 16, xb + (size_t)bs * 80 + (size_t)c * 16);
        }
        cp_commit();
    }

    // ---- wait for lb_scatter's g_lb0 to be complete & visible ----
    cudaGridDependencySynchronize();

    const int lb0 = g_lb0[blockIdx.x];
    const int n   = g_lb0[blockIdx.x + 1] - lb0;   // pu entries in window (<= CHUNK)
    for (int i = tid; i < n; i += THREADS)
        spu[i] = (uint16_t)(__ldg(pu + lb0 + i) - bs);   // offsets in [0, CHUNK)

    #pragma unroll
    for (int t = 0; t < NTILES; t++) {
        if (t + 1 < NTILES) {
            const int tb  = bs + (t + 1) * TILE;
            const int vt  = min(TILE, S - tb);
            const int vt5 = vt * 5;
            uint32_t dst = (uint32_t)__cvta_generic_to_shared(&sx[(t + 1) & 1][0]);
            #pragma unroll
            for (int r = 0; r < 5; r++) {
                const int c = tid + r * THREADS;
                if (c < vt5) cp_async16(dst + c * 16, xb + (size_t)tb * 80 + (size_t)c * 16);
            }
            cp_commit();
            cp_wait<1>();
        } else {
            cp_wait<0>();
        }
        __syncthreads();

        const int s = bs + t * TILE + tid;
        if (s < S) {
            const float4* __restrict__ row = &sx[t & 1][tid * 5];

            // ---- exact argmax over 20 f32 (first-index tie-break) ----
            const float4 q0 = row[0], q1 = row[1], q2 = row[2], q3 = row[3], q4 = row[4];
            const float g0 = fmaxf(fmaxf(q0.x, q0.y), fmaxf(q0.z, q0.w));
            const float g1 = fmaxf(fmaxf(q1.x, q1.y), fmaxf(q1.z, q1.w));
            const float g2 = fmaxf(fmaxf(q2.x, q2.y), fmaxf(q2.z, q2.w));
            const float g3 = fmaxf(fmaxf(q3.x, q3.y), fmaxf(q3.z, q3.w));
            const float g4 = fmaxf(fmaxf(q4.x, q4.y), fmaxf(q4.z, q4.w));
            const float M  = fmaxf(g4, fmaxf(fmaxf(g0, g1), fmaxf(g2, g3)));

            int gi = 4;
            gi = (g3 == M) ? 3 : gi;
            gi = (g2 == M) ? 2 : gi;
            gi = (g1 == M) ? 1 : gi;
            gi = (g0 == M) ? 0 : gi;

            const float4 qw = row[gi];           // LDS reload of winning quad
            int li = 3;
            li = (qw.z == M) ? 2 : li;
            li = (qw.y == M) ? 1 : li;
            li = (qw.x == M) ? 0 : li;
            const int e = gi * 4 + li;

            // ---- expert Linear(2,2) + softmax(2) ----
            const float2 hv = h2[s];
            const float4 w  = sW[e];
            const float2 bb = sB[e];
            const float y0 = fmaf(hv.x, w.x, fmaf(hv.y, w.y, bb.x));
            const float y1 = fmaf(hv.x, w.z, fmaf(hv.y, w.w, bb.y));
            const float ed  = __expf(y1 - y0);
            const float inv = __fdividef(1.0f, 1.0f + ed);
            float2 yo;
            yo.x = inv;
            yo.y = ed * inv;

            outy[s] = yo;

            // ---- permutation: lb = lb0 + lower_bound(spu, s - bs) ----
            const int ls = t * TILE + tid;       // local target in [0, CHUNK)
            int lo = 0, hi = n;
            while (lo < hi) {
                int mid = (lo + hi) >> 1;
                if ((int)spu[mid] < ls) lo = mid + 1; else hi = mid;
            }
            const int  cur  = (lo < n) ? (int)spu[lo] : 0x7fffffff;
            const bool ispu = (cur == ls);
            const int  dest = ispu ? (lb0 + lo) : (P + s - lb0 - lo);
            outy2[dest] = yo;
        }
        __syncthreads();
    }
}

extern "C" void kernel_launch(void* const* d_in, const int* in_sizes, int n_in,
                              void* d_out, int out_size)
{
    const float* x  = (const float*)d_in[0];   // [1, S, 20]
    const float* h  = (const float*)d_in[1];   // [S, 2]
    const float* W  = (const float*)d_in[2];   // [20, 2, 2]
    const float* b  = (const float*)d_in[3];   // [20, 2]
    const int*   pu = (const int*)  d_in[4];   // [P]

    const int S = in_sizes[1] / 2;
    const int P = in_sizes[4];
    const int blocks = (S + CHUNK - 1) / CHUNK;

    const int sthreads = (P + 7) / 8;
    lb_scatter<<<(sthreads + 255) / 256, 256>>>(pu, P, blocks);

    cudaLaunchAttribute attrs[1];
    attrs[0].id = cudaLaunchAttributeProgrammaticStreamSerialization;
    attrs[0].val.programmaticStreamSerializationAllowed = 1;

    cudaLaunchConfig_t cfg = {};
    cfg.gridDim  = dim3((unsigned)blocks, 1, 1);
    cfg.blockDim = dim3(THREADS, 1, 1);
    cfg.dynamicSmemBytes = 0;
    cfg.stream = 0;
    cfg.attrs = attrs;
    cfg.numAttrs = 1;

    cudaLaunchKernelEx(&cfg, verblizer_kernel, x, h, W, b, pu, S, P, (float*)d_out);
}

// round 13
// speedup vs baseline: 1.1558x; 1.1185x over previous
#include <cuda_runtime.h>
#include <cstdint>

// Verblizer: per-token argmax(20) -> expert Linear(2,2) -> softmax(2) -> y,
// plus permuted copy y2 (pu rows first, then non-pu rows in order).
// d_out[0..2S) = y, d_out[2S..4S) = y2.
//
// R8 structure (proven best): lb_scatter (PDL) + independent streaming
// blocks, CHUNK=1024. R13 single delta: spu staged as u16 offsets
// (smem 46 -> 44KB -> 5 resident blocks/SM).

#define THREADS 256
#define TILE    256
#define NTILES  4
#define CHUNK   (TILE * NTILES)      // 1024 tokens per block
#define MAXB    65537

__device__ int g_lb0[MAXB];

// ---- vectorized streaming scatter: each thread owns pu[8i .. 8i+8) ----
__global__ void lb_scatter(const int* __restrict__ pu, int P, int nblocks)
{
    const int i = blockIdx.x * blockDim.x + threadIdx.x;
    const int base = i * 8;
    if (base < P) {
        int v[9];
        const int4 a = __ldg(reinterpret_cast<const int4*>(pu) + 2 * i);
        v[0] = a.x; v[1] = a.y; v[2] = a.z; v[3] = a.w;
        if (base + 8 <= P) {
            const int4 c = __ldg(reinterpret_cast<const int4*>(pu) + 2 * i + 1);
            v[4] = c.x; v[5] = c.y; v[6] = c.z; v[7] = c.w;
            v[8] = (base + 8 < P) ? __ldg(pu + base + 8) : 0x7fffffff;
        } else {
            #pragma unroll
            for (int k = 4; k <= 8; k++)
                v[k] = (base + k < P) ? __ldg(pu + base + k) : 0x7fffffff;
        }

        if (i == 0) {
            for (int j = 0; j <= nblocks && j * CHUNK <= v[0]; j++) g_lb0[j] = 0;
        }

        #pragma unroll
        for (int k = 0; k < 8; k++) {
            const int m = base + k;
            if (m >= P) break;
            const int hiv = v[k + 1];
            int j  = v[k] / CHUNK + 1;
            int jh = (hiv == 0x7fffffff) ? nblocks : hiv / CHUNK;
            if (jh > nblocks) jh = nblocks;
            for (; j <= jh; j++) g_lb0[j] = m + 1;
        }
    }
    cudaTriggerProgrammaticLaunchCompletion();
}

__device__ __forceinline__ void cp_async16(uint32_t smem_dst, const void* gptr) {
    asm volatile("cp.async.cg.shared.global [%0], [%1], 16;\n" :: "r"(smem_dst), "l"(gptr));
}
__device__ __forceinline__ void cp_commit() { asm volatile("cp.async.commit_group;\n"); }
template<int N> __device__ __forceinline__ void cp_wait() {
    asm volatile("cp.async.wait_group %0;\n" :: "n"(N));
}

__global__ __launch_bounds__(THREADS)
void verblizer_kernel(const float*  __restrict__ x,
                      const float*  __restrict__ h,
                      const float*  __restrict__ W,
                      const float*  __restrict__ b,
                      const int*    __restrict__ pu,
                      int S, int P,
                      float* __restrict__ out)
{
    __shared__ float4   sx[2][TILE * 5];   // 2 x 20KB staged x tiles
    __shared__ uint16_t spu[CHUNK];        // 2KB pu window (offsets from bs)
    __shared__ float4   sW[20];
    __shared__ float2   sB[20];

    const int tid = threadIdx.x;
    const int bs  = blockIdx.x * CHUNK;

    // ---- prelude: independent of g_lb0, overlaps the scatter kernel ----
    if (tid < 20) {
        sW[tid] = reinterpret_cast<const float4*>(W)[tid];
        sB[tid] = reinterpret_cast<const float2*>(b)[tid];
    }

    const char* __restrict__ xb = reinterpret_cast<const char*>(x);
    const float2* __restrict__ h2 = reinterpret_cast<const float2*>(h);
    float2* __restrict__ outy  = reinterpret_cast<float2*>(out);
    float2* __restrict__ outy2 = reinterpret_cast<float2*>(out + (size_t)2 * S);

    // stage tile 0 (x stream only)
    {
        const int vt  = min(TILE, S - bs);
        const int vt5 = vt * 5;
        uint32_t dst = (uint32_t)__cvta_generic_to_shared(&sx[0][0]);
        #pragma unroll
        for (int r = 0; r < 5; r++) {
            const int c = tid + r * THREADS;
            if (c < vt5) cp_async16(dst + c * 16, xb + (size_t)bs * 80 + (size_t)c * 16);
        }
        cp_commit();
    }

    // ---- wait for lb_scatter's g_lb0 to be complete & visible ----
    cudaGridDependencySynchronize();

    const int lb0 = g_lb0[blockIdx.x];
    const int n   = g_lb0[blockIdx.x + 1] - lb0;   // pu entries in window (<= CHUNK)
    for (int i = tid; i < n; i += THREADS)
        spu[i] = (uint16_t)(__ldg(pu + lb0 + i) - bs);   // offsets in [0, CHUNK)

    #pragma unroll
    for (int t = 0; t < NTILES; t++) {
        if (t + 1 < NTILES) {
            const int tb  = bs + (t + 1) * TILE;
            const int vt  = min(TILE, S - tb);
            const int vt5 = vt * 5;
            uint32_t dst = (uint32_t)__cvta_generic_to_shared(&sx[(t + 1) & 1][0]);
            #pragma unroll
            for (int r = 0; r < 5; r++) {
                const int c = tid + r * THREADS;
                if (c < vt5) cp_async16(dst + c * 16, xb + (size_t)tb * 80 + (size_t)c * 16);
            }
            cp_commit();
            cp_wait<1>();
        } else {
            cp_wait<0>();
        }
        __syncthreads();

        const int s = bs + t * TILE + tid;
        if (s < S) {
            const float4* __restrict__ row = &sx[t & 1][tid * 5];

            // ---- exact argmax over 20 f32 (first-index tie-break) ----
            const float4 q0 = row[0], q1 = row[1], q2 = row[2], q3 = row[3], q4 = row[4];
            const float g0 = fmaxf(fmaxf(q0.x, q0.y), fmaxf(q0.z, q0.w));
            const float g1 = fmaxf(fmaxf(q1.x, q1.y), fmaxf(q1.z, q1.w));
            const float g2 = fmaxf(fmaxf(q2.x, q2.y), fmaxf(q2.z, q2.w));
            const float g3 = fmaxf(fmaxf(q3.x, q3.y), fmaxf(q3.z, q3.w));
            const float g4 = fmaxf(fmaxf(q4.x, q4.y), fmaxf(q4.z, q4.w));
            const float M  = fmaxf(g4, fmaxf(fmaxf(g0, g1), fmaxf(g2, g3)));

            int gi = 4;
            gi = (g3 == M) ? 3 : gi;
            gi = (g2 == M) ? 2 : gi;
            gi = (g1 == M) ? 1 : gi;
            gi = (g0 == M) ? 0 : gi;

            const float4 qw = row[gi];           // LDS reload of winning quad
            int li = 3;
            li = (qw.z == M) ? 2 : li;
            li = (qw.y == M) ? 1 : li;
            li = (qw.x == M) ? 0 : li;
            const int e = gi * 4 + li;

            // ---- expert Linear(2,2) + softmax(2) ----
            const float2 hv = h2[s];
            const float4 w  = sW[e];
            const float2 bb = sB[e];
            const float y0 = fmaf(hv.x, w.x, fmaf(hv.y, w.y, bb.x));
            const float y1 = fmaf(hv.x, w.z, fmaf(hv.y, w.w, bb.y));
            const float ed  = __expf(y1 - y0);
            const float inv = __fdividef(1.0f, 1.0f + ed);
            float2 yo;
            yo.x = inv;
            yo.y = ed * inv;

            outy[s] = yo;

            // ---- permutation: lb = lb0 + lower_bound(spu, s - bs) ----
            const int ls = t * TILE + tid;       // local target in [0, CHUNK)
            int lo = 0, hi = n;
            while (lo < hi) {
                int mid = (lo + hi) >> 1;
                if ((int)spu[mid] < ls) lo = mid + 1; else hi = mid;
            }
            const int  cur  = (lo < n) ? (int)spu[lo] : 0x7fffffff;
            const bool ispu = (cur == ls);
            const int  dest = ispu ? (lb0 + lo) : (P + s - lb0 - lo);
            outy2[dest] = yo;
        }
        __syncthreads();
    }
}

extern "C" void kernel_launch(void* const* d_in, const int* in_sizes, int n_in,
                              void* d_out, int out_size)
{
    const float* x  = (const float*)d_in[0];   // [1, S, 20]
    const float* h  = (const float*)d_in[1];   // [S, 2]
    const float* W  = (const float*)d_in[2];   // [20, 2, 2]
    const float* b  = (const float*)d_in[3];   // [20, 2]
    const int*   pu = (const int*)  d_in[4];   // [P]

    const int S = in_sizes[1] / 2;
    const int P = in_sizes[4];
    const int blocks = (S + CHUNK - 1) / CHUNK;

    const int sthreads = (P + 7) / 8;
    lb_scatter<<<(sthreads + 255) / 256, 256>>>(pu, P, blocks);

    cudaLaunchAttribute attrs[1];
    attrs[0].id = cudaLaunchAttributeProgrammaticStreamSerialization;
    attrs[0].val.programmaticStreamSerializationAllowed = 1;

    cudaLaunchConfig_t cfg = {};
    cfg.gridDim  = dim3((unsigned)blocks, 1, 1);
    cfg.blockDim = dim3(THREADS, 1, 1);
    cfg.dynamicSmemBytes = 0;
    cfg.stream = 0;
    cfg.attrs = attrs;
    cfg.numAttrs = 1;

    cudaLaunchKernelEx(&cfg, verblizer_kernel, x, h, W, b, pu, S, P, (float*)d_out);
}